// round 1
// baseline (speedup 1.0000x reference)
#include <cuda_runtime.h>
#include <math.h>

#define SEQ 4096
#define DIM 1280
#define NH 20
#define HD 64
#define FFNDIM 5120
#define SEGLEN 512

// ---------------- scratch (no allocations allowed) ----------------
__device__ float g_xln[SEQ * DIM];
__device__ float g_q[SEQ * DIM];
__device__ float g_k[SEQ * DIM];
__device__ float g_v[SEQ * DIM];
__device__ float g_attn[SEQ * DIM];
__device__ float g_h[SEQ * DIM];
__device__ float g_yln[SEQ * DIM];
__device__ float g_mid[(size_t)SEQ * FFNDIM];

// ---------------- LayerNorm: one block per row ----------------
__global__ void ln_kernel(const float* __restrict__ x, const float* __restrict__ g,
                          const float* __restrict__ b, float* __restrict__ y) {
    int row = blockIdx.x;
    const float* xr = x + (size_t)row * DIM;
    float v[5];
    float s = 0.f, sq = 0.f;
#pragma unroll
    for (int i = 0; i < 5; i++) {
        v[i] = xr[threadIdx.x + i * 256];
        s += v[i];
        sq += v[i] * v[i];
    }
    __shared__ float red[64];
#pragma unroll
    for (int o = 16; o > 0; o >>= 1) {
        s += __shfl_xor_sync(0xFFFFFFFFu, s, o);
        sq += __shfl_xor_sync(0xFFFFFFFFu, sq, o);
    }
    int w = threadIdx.x >> 5, l = threadIdx.x & 31;
    if (l == 0) { red[w] = s; red[w + 8] = sq; }
    __syncthreads();
    if (threadIdx.x < 32) {
        float ss = (threadIdx.x < 8) ? red[threadIdx.x] : 0.f;
        float qq = (threadIdx.x < 8) ? red[threadIdx.x + 8] : 0.f;
#pragma unroll
        for (int o = 4; o > 0; o >>= 1) {
            ss += __shfl_xor_sync(0xFFFFFFFFu, ss, o);
            qq += __shfl_xor_sync(0xFFFFFFFFu, qq, o);
        }
        if (threadIdx.x == 0) { red[32] = ss; red[33] = qq; }
    }
    __syncthreads();
    float mu  = red[32] * (1.f / DIM);
    float var = red[33] * (1.f / DIM) - mu * mu;
    float inv = rsqrtf(var + 1e-5f);
    float* yr = y + (size_t)row * DIM;
#pragma unroll
    for (int i = 0; i < 5; i++) {
        int c = threadIdx.x + i * 256;
        yr[c] = (v[i] - mu) * inv * g[c] + b[c];
    }
}

// ---------------- SGEMM 128x128x8, 8x8 per-thread ----------------
#define EPI_NONE 0
#define EPI_BIAS 1
#define EPI_GELU 2
#define EPI_BIAS_RES 3

template <int EPI>
__global__ __launch_bounds__(256) void sgemm_k(
    const float* __restrict__ A, const float* __restrict__ B,
    const float* __restrict__ bias, const float* __restrict__ res,
    float* __restrict__ C, int M, int N, int K) {
    __shared__ __align__(16) float As[8][128];
    __shared__ __align__(16) float Bs[8][128];
    int tid = threadIdx.x;
    int br = blockIdx.y * 128, bc = blockIdx.x * 128;
    int aRow = tid >> 1, aCol = (tid & 1) * 4;
    int bRow = tid >> 5, bCol = (tid & 31) * 4;
    const float* Ap = A + (size_t)(br + aRow) * K + aCol;
    const float* Bp = B + (size_t)bRow * N + bc + bCol;
    float acc[8][8] = {};
    int tr = (tid >> 4) * 8, tc = (tid & 15) * 8;

    for (int k0 = 0; k0 < K; k0 += 8) {
        float4 a = *(const float4*)(Ap + k0);
        As[aCol + 0][aRow] = a.x;
        As[aCol + 1][aRow] = a.y;
        As[aCol + 2][aRow] = a.z;
        As[aCol + 3][aRow] = a.w;
        *(float4*)(&Bs[bRow][bCol]) = *(const float4*)(Bp + (size_t)k0 * N);
        __syncthreads();
#pragma unroll
        for (int k = 0; k < 8; k++) {
            float4 a0 = *(const float4*)&As[k][tr];
            float4 a1 = *(const float4*)&As[k][tr + 4];
            float4 b0 = *(const float4*)&Bs[k][tc];
            float4 b1 = *(const float4*)&Bs[k][tc + 4];
            float ra[8] = {a0.x, a0.y, a0.z, a0.w, a1.x, a1.y, a1.z, a1.w};
            float rb[8] = {b0.x, b0.y, b0.z, b0.w, b1.x, b1.y, b1.z, b1.w};
#pragma unroll
            for (int i = 0; i < 8; i++)
#pragma unroll
                for (int j = 0; j < 8; j++) acc[i][j] += ra[i] * rb[j];
        }
        __syncthreads();
    }

#pragma unroll
    for (int i = 0; i < 8; i++) {
        int row = br + tr + i;
#pragma unroll
        for (int j = 0; j < 8; j++) {
            int col = bc + tc + j;
            float vv = acc[i][j];
            if (EPI == EPI_BIAS || EPI == EPI_GELU || EPI == EPI_BIAS_RES)
                vv += bias[col];
            if (EPI == EPI_GELU)
                vv = 0.5f * vv * (1.f + erff(vv * 0.70710678118654752f));
            if (EPI == EPI_BIAS_RES)
                vv += res[(size_t)row * N + col];
            C[(size_t)row * N + col] = vv;
        }
    }
}

// ---------------- block-diagonal attention ----------------
// block = (32-query tile, head, segment). smem: scoresT[512][33], Qs[32][65], KVs[64][65]
#define SCORE_PITCH 33
#define QS_OFF (512 * SCORE_PITCH)
#define KV_OFF (QS_OFF + 32 * 65)
#define ATTN_SMEM_FLOATS (KV_OFF + 64 * 65)

__global__ __launch_bounds__(256) void attn_kernel(
    const float* __restrict__ Q, const float* __restrict__ Kg,
    const float* __restrict__ V, float* __restrict__ O) {
    extern __shared__ float sm[];
    float* scoresT = sm;
    float* Qs = sm + QS_OFF;
    float* KVs = sm + KV_OFF;

    int tid = threadIdx.x;
    int qt = blockIdx.x;   // 0..15
    int hh = blockIdx.y;   // 0..19
    int sg = blockIdx.z;   // 0..7
    int qbase = sg * SEGLEN + qt * 32;
    int kbase = sg * SEGLEN;
    int colbase = hh * HD;

    // load Q tile (scaled by 1/sqrt(64))
#pragma unroll
    for (int i = 0; i < 8; i++) {
        int e = tid + i * 256;
        int q = e >> 6, d = e & 63;
        Qs[q * 65 + d] = Q[(size_t)(qbase + q) * DIM + colbase + d] * 0.125f;
    }
    int ql = tid & 31;
    int grp = tid >> 5;

    // Phase A: scores
    for (int kt = 0; kt < 8; kt++) {
        __syncthreads();
#pragma unroll
        for (int i = 0; i < 16; i++) {
            int e = tid + i * 256;
            int k = e >> 6, d = e & 63;
            KVs[k * 65 + d] = Kg[(size_t)(kbase + kt * 64 + k) * DIM + colbase + d];
        }
        __syncthreads();
        float acc[8] = {};
#pragma unroll
        for (int d = 0; d < 64; d++) {
            float qv = Qs[ql * 65 + d];
#pragma unroll
            for (int j = 0; j < 8; j++)
                acc[j] += qv * KVs[(grp * 8 + j) * 65 + d];
        }
#pragma unroll
        for (int j = 0; j < 8; j++)
            scoresT[(kt * 64 + grp * 8 + j) * SCORE_PITCH + ql] = acc[j];
    }
    __syncthreads();

    // Phase B: softmax (warp w handles queries w, w+8, w+16, w+24)
    {
        int w = tid >> 5, l = tid & 31;
        for (int qi = 0; qi < 4; qi++) {
            int q = w + qi * 8;
            float vals[16];
            float m = -1e30f;
#pragma unroll
            for (int s = 0; s < 16; s++) {
                vals[s] = scoresT[(l + s * 32) * SCORE_PITCH + q];
                m = fmaxf(m, vals[s]);
            }
#pragma unroll
            for (int o = 16; o > 0; o >>= 1) m = fmaxf(m, __shfl_xor_sync(0xFFFFFFFFu, m, o));
            float sum = 0.f;
#pragma unroll
            for (int s = 0; s < 16; s++) {
                float e = __expf(vals[s] - m);
                vals[s] = e;
                sum += e;
            }
#pragma unroll
            for (int o = 16; o > 0; o >>= 1) sum += __shfl_xor_sync(0xFFFFFFFFu, sum, o);
            float r = 1.f / sum;
#pragma unroll
            for (int s = 0; s < 16; s++)
                scoresT[(l + s * 32) * SCORE_PITCH + q] = vals[s] * r;
        }
    }

    // Phase C: P@V
    float o[8] = {};
    for (int vt = 0; vt < 8; vt++) {
        __syncthreads();
#pragma unroll
        for (int i = 0; i < 16; i++) {
            int e = tid + i * 256;
            int k = e >> 6, d = e & 63;
            KVs[k * 65 + d] = V[(size_t)(kbase + vt * 64 + k) * DIM + colbase + d];
        }
        __syncthreads();
#pragma unroll
        for (int kk = 0; kk < 64; kk++) {
            float p = scoresT[(vt * 64 + kk) * SCORE_PITCH + ql];
#pragma unroll
            for (int j = 0; j < 8; j++)
                o[j] += p * KVs[kk * 65 + grp * 8 + j];
        }
    }

    // write O at [seq, head*64 + d]
    float4* dst = (float4*)&O[(size_t)(qbase + ql) * DIM + colbase + grp * 8];
    dst[0] = make_float4(o[0], o[1], o[2], o[3]);
    dst[1] = make_float4(o[4], o[5], o[6], o[7]);
}

// ---------------- launch ----------------
extern "C" void kernel_launch(void* const* d_in, const int* in_sizes, int n_in,
                              void* d_out, int out_size) {
    const float* hidden = (const float*)d_in[0];
    const float* Wq = (const float*)d_in[2];
    const float* bq = (const float*)d_in[3];
    const float* Wk = (const float*)d_in[4];
    const float* Wv = (const float*)d_in[5];
    const float* bv = (const float*)d_in[6];
    const float* Wo = (const float*)d_in[7];
    const float* bo = (const float*)d_in[8];
    const float* g1 = (const float*)d_in[9];
    const float* b1 = (const float*)d_in[10];
    const float* Wf1 = (const float*)d_in[11];
    const float* bf1 = (const float*)d_in[12];
    const float* Wf2 = (const float*)d_in[13];
    const float* bf2 = (const float*)d_in[14];
    const float* g2 = (const float*)d_in[15];
    const float* b2 = (const float*)d_in[16];
    float* out = (float*)d_out;

    float *xln, *q, *k, *v, *attn, *h, *yln, *mid;
    cudaGetSymbolAddress((void**)&xln, g_xln);
    cudaGetSymbolAddress((void**)&q, g_q);
    cudaGetSymbolAddress((void**)&k, g_k);
    cudaGetSymbolAddress((void**)&v, g_v);
    cudaGetSymbolAddress((void**)&attn, g_attn);
    cudaGetSymbolAddress((void**)&h, g_h);
    cudaGetSymbolAddress((void**)&yln, g_yln);
    cudaGetSymbolAddress((void**)&mid, g_mid);

    const int ATTN_SMEM = ATTN_SMEM_FLOATS * 4;
    cudaFuncSetAttribute(attn_kernel, cudaFuncAttributeMaxDynamicSharedMemorySize, ATTN_SMEM);

    dim3 gD(DIM / 128, SEQ / 128);
    dim3 gF(FFNDIM / 128, SEQ / 128);

    // LN1
    ln_kernel<<<SEQ, 256>>>(hidden, g1, b1, xln);
    // QKV
    sgemm_k<EPI_BIAS><<<gD, 256>>>(xln, Wq, bq, nullptr, q, SEQ, DIM, DIM);
    sgemm_k<EPI_NONE><<<gD, 256>>>(xln, Wk, nullptr, nullptr, k, SEQ, DIM, DIM);
    sgemm_k<EPI_BIAS><<<gD, 256>>>(xln, Wv, bv, nullptr, v, SEQ, DIM, DIM);
    // attention (block-diagonal, 512-token segments)
    attn_kernel<<<dim3(16, NH, 8), 256, ATTN_SMEM>>>(q, k, v, attn);
    // O proj + residual
    sgemm_k<EPI_BIAS_RES><<<gD, 256>>>(attn, Wo, bo, hidden, h, SEQ, DIM, DIM);
    // LN2
    ln_kernel<<<SEQ, 256>>>(h, g2, b2, yln);
    // FFN
    sgemm_k<EPI_GELU><<<gF, 256>>>(yln, Wf1, bf1, nullptr, mid, SEQ, FFNDIM, DIM);
    sgemm_k<EPI_BIAS_RES><<<gD, 256>>>(mid, Wf2, bf2, h, out, SEQ, DIM, FFNDIM);
}

// round 4
// speedup vs baseline: 2.1668x; 2.1668x over previous
#include <cuda_runtime.h>
#include <math.h>
#include <stdint.h>

#define SEQ 4096
#define DIM 1280
#define NH 20
#define HD 64
#define FFNDIM 5120
#define SEGLEN 512

// ---------------- scratch (no allocations allowed) ----------------
__device__ float g_xln[SEQ * DIM];
__device__ float g_q[SEQ * DIM];
__device__ float g_k[SEQ * DIM];
__device__ float g_v[SEQ * DIM];
__device__ float g_attn[SEQ * DIM];
__device__ float g_h[SEQ * DIM];
__device__ float g_yln[SEQ * DIM];
__device__ float g_mid[(size_t)SEQ * FFNDIM];
// transposed weights (K-major, [N,K])
__device__ float g_wqt[DIM * DIM];
__device__ float g_wkt[DIM * DIM];
__device__ float g_wvt[DIM * DIM];
__device__ float g_wot[DIM * DIM];
__device__ float g_wf1t[(size_t)FFNDIM * DIM];
__device__ float g_wf2t[(size_t)DIM * FFNDIM];

// ---------------- helpers ----------------
__device__ __forceinline__ uint32_t f2tf(float x) {
    uint32_t u;
    asm("cvt.rna.tf32.f32 %0, %1;" : "=r"(u) : "f"(x));
    return u;
}

__device__ __forceinline__ void mma_tf32(float* d, const uint32_t* a,
                                         const uint32_t* b) {
    asm volatile(
        "mma.sync.aligned.m16n8k8.row.col.f32.tf32.tf32.f32 "
        "{%0,%1,%2,%3}, {%4,%5,%6,%7}, {%8,%9}, {%0,%1,%2,%3};"
        : "+f"(d[0]), "+f"(d[1]), "+f"(d[2]), "+f"(d[3])
        : "r"(a[0]), "r"(a[1]), "r"(a[2]), "r"(a[3]),
          "r"(b[0]), "r"(b[1]));
}

// ---------------- transpose: out[C,R] = in[R,C]^T ----------------
__global__ void transpose_k(const float* __restrict__ in, float* __restrict__ out,
                            int R, int C) {
    __shared__ float t[32][33];
    int c = blockIdx.x * 32 + threadIdx.x;
    int r = blockIdx.y * 32 + threadIdx.y;
#pragma unroll
    for (int j = 0; j < 32; j += 8)
        t[threadIdx.y + j][threadIdx.x] = in[(size_t)(r + j) * C + c];
    __syncthreads();
    int oc = blockIdx.y * 32 + threadIdx.x;
    int orr = blockIdx.x * 32 + threadIdx.y;
#pragma unroll
    for (int j = 0; j < 32; j += 8)
        out[(size_t)(orr + j) * R + oc] = t[threadIdx.x][threadIdx.y + j];
}

// ---------------- LayerNorm ----------------
__global__ void ln_kernel(const float* __restrict__ x, const float* __restrict__ g,
                          const float* __restrict__ b, float* __restrict__ y) {
    int row = blockIdx.x;
    const float* xr = x + (size_t)row * DIM;
    float v[5];
    float s = 0.f, sq = 0.f;
#pragma unroll
    for (int i = 0; i < 5; i++) {
        v[i] = xr[threadIdx.x + i * 256];
        s += v[i];
        sq += v[i] * v[i];
    }
    __shared__ float red[64];
#pragma unroll
    for (int o = 16; o > 0; o >>= 1) {
        s += __shfl_xor_sync(0xFFFFFFFFu, s, o);
        sq += __shfl_xor_sync(0xFFFFFFFFu, sq, o);
    }
    int w = threadIdx.x >> 5, l = threadIdx.x & 31;
    if (l == 0) { red[w] = s; red[w + 8] = sq; }
    __syncthreads();
    if (threadIdx.x < 32) {
        float ss = (threadIdx.x < 8) ? red[threadIdx.x] : 0.f;
        float qq = (threadIdx.x < 8) ? red[threadIdx.x + 8] : 0.f;
#pragma unroll
        for (int o = 4; o > 0; o >>= 1) {
            ss += __shfl_xor_sync(0xFFFFFFFFu, ss, o);
            qq += __shfl_xor_sync(0xFFFFFFFFu, qq, o);
        }
        if (threadIdx.x == 0) { red[32] = ss; red[33] = qq; }
    }
    __syncthreads();
    float mu  = red[32] * (1.f / DIM);
    float var = red[33] * (1.f / DIM) - mu * mu;
    float inv = rsqrtf(var + 1e-5f);
    float* yr = y + (size_t)row * DIM;
#pragma unroll
    for (int i = 0; i < 5; i++) {
        int c = threadIdx.x + i * 256;
        yr[c] = (v[i] - mu) * inv * g[c] + b[c];
    }
}

// ---------------- tf32 mma.sync GEMM: C[M,Ntot] = A[M,K] @ Bt[N,K]^T ----------------
#define EPI_NONE 0
#define EPI_BIAS 1
#define EPI_GELU 2
#define EPI_BIAS_RES 3

#define BK 32
#define PITCH 36                  // BK + 4 pad: (36*g + c) mod 32 bijective over warp
#define TSZ (128 * PITCH)         // floats per tile buffer
#define GEMM_DSMEM (4 * TSZ * 4)  // 2 buffers x (A + B) = 73728 bytes

template <int EPI>
__global__ __launch_bounds__(256) void mma_gemm(
    const float* __restrict__ A, const float* __restrict__ Bt,
    const float* __restrict__ bias, const float* __restrict__ res,
    float* __restrict__ C, int Ntot, int K) {
    extern __shared__ float sm[];
    // layout: As0, As1, Bs0, Bs1
    float* Asb[2] = {sm, sm + TSZ};
    float* Bsb[2] = {sm + 2 * TSZ, sm + 3 * TSZ};

    int tid = threadIdx.x;
    int wid = tid >> 5, lane = tid & 31;
    int warp_m = wid & 1;          // 0..1 -> 64 rows each
    int warp_n = wid >> 1;         // 0..3 -> 32 cols each
    int g = lane >> 2, c = lane & 3;
    int br = blockIdx.y * 128, bc = blockIdx.x * 128;

    int rowq = tid >> 3;           // 0..31
    int f4 = tid & 7;              // float4 slot in a 32-float row
    const float* Abase = A + (size_t)br * K + f4 * 4;
    const float* Bbase = Bt + (size_t)bc * K + f4 * 4;

    float acc[4][4][4];
#pragma unroll
    for (int i = 0; i < 4; i++)
#pragma unroll
        for (int j = 0; j < 4; j++)
#pragma unroll
            for (int u = 0; u < 4; u++) acc[i][j][u] = 0.f;

    const int NIT = K / BK;

    float4 av[4], bv[4];
    // load tile 0
#pragma unroll
    for (int p = 0; p < 4; p++) {
        int row = p * 32 + rowq;
        av[p] = *(const float4*)(Abase + (size_t)row * K);
        bv[p] = *(const float4*)(Bbase + (size_t)row * K);
    }
#pragma unroll
    for (int p = 0; p < 4; p++) {
        int row = p * 32 + rowq;
        uint4 ta = make_uint4(f2tf(av[p].x), f2tf(av[p].y), f2tf(av[p].z), f2tf(av[p].w));
        uint4 tb = make_uint4(f2tf(bv[p].x), f2tf(bv[p].y), f2tf(bv[p].z), f2tf(bv[p].w));
        *(uint4*)&Asb[0][row * PITCH + f4 * 4] = ta;
        *(uint4*)&Bsb[0][row * PITCH + f4 * 4] = tb;
    }
    __syncthreads();

    for (int it = 0; it < NIT; it++) {
        int cur = it & 1;
        bool more = (it + 1) < NIT;
        if (more) {
            int k0 = (it + 1) * BK;
#pragma unroll
            for (int p = 0; p < 4; p++) {
                int row = p * 32 + rowq;
                av[p] = *(const float4*)(Abase + (size_t)row * K + k0);
                bv[p] = *(const float4*)(Bbase + (size_t)row * K + k0);
            }
        }
        const uint32_t* As = (const uint32_t*)Asb[cur];
        const uint32_t* Bs = (const uint32_t*)Bsb[cur];
#pragma unroll
        for (int ks = 0; ks < 4; ks++) {
            int k0 = ks * 8;
            uint32_t af[4][4], bf[4][2];
#pragma unroll
            for (int mt = 0; mt < 4; mt++) {
                int rm = warp_m * 64 + mt * 16 + g;
                af[mt][0] = As[rm * PITCH + k0 + c];
                af[mt][1] = As[(rm + 8) * PITCH + k0 + c];
                af[mt][2] = As[rm * PITCH + k0 + c + 4];
                af[mt][3] = As[(rm + 8) * PITCH + k0 + c + 4];
            }
#pragma unroll
            for (int nt = 0; nt < 4; nt++) {
                int rn = warp_n * 32 + nt * 8 + g;
                bf[nt][0] = Bs[rn * PITCH + k0 + c];
                bf[nt][1] = Bs[rn * PITCH + k0 + c + 4];
            }
#pragma unroll
            for (int mt = 0; mt < 4; mt++)
#pragma unroll
                for (int nt = 0; nt < 4; nt++)
                    mma_tf32(acc[mt][nt], af[mt], bf[nt]);
        }
        if (more) {
            int nxt = cur ^ 1;
#pragma unroll
            for (int p = 0; p < 4; p++) {
                int row = p * 32 + rowq;
                uint4 ta = make_uint4(f2tf(av[p].x), f2tf(av[p].y), f2tf(av[p].z), f2tf(av[p].w));
                uint4 tb = make_uint4(f2tf(bv[p].x), f2tf(bv[p].y), f2tf(bv[p].z), f2tf(bv[p].w));
                *(uint4*)&Asb[nxt][row * PITCH + f4 * 4] = ta;
                *(uint4*)&Bsb[nxt][row * PITCH + f4 * 4] = tb;
            }
        }
        __syncthreads();
    }

    // epilogue
#pragma unroll
    for (int mt = 0; mt < 4; mt++) {
#pragma unroll
        for (int nt = 0; nt < 4; nt++) {
            int col = bc + warp_n * 32 + nt * 8 + c * 2;
#pragma unroll
            for (int half = 0; half < 2; half++) {
                int row = br + warp_m * 64 + mt * 16 + g + half * 8;
                float x0 = acc[mt][nt][half * 2 + 0];
                float x1 = acc[mt][nt][half * 2 + 1];
                if (EPI == EPI_BIAS || EPI == EPI_GELU || EPI == EPI_BIAS_RES) {
                    x0 += bias[col];
                    x1 += bias[col + 1];
                }
                if (EPI == EPI_GELU) {
                    x0 = 0.5f * x0 * (1.f + erff(x0 * 0.70710678118654752f));
                    x1 = 0.5f * x1 * (1.f + erff(x1 * 0.70710678118654752f));
                }
                if (EPI == EPI_BIAS_RES) {
                    float2 r2 = *(const float2*)(res + (size_t)row * Ntot + col);
                    x0 += r2.x;
                    x1 += r2.y;
                }
                *(float2*)(C + (size_t)row * Ntot + col) = make_float2(x0, x1);
            }
        }
    }
}

// ---------------- block-diagonal attention (fp32, unchanged) ----------------
#define SCORE_PITCH 33
#define QS_OFF (512 * SCORE_PITCH)
#define KV_OFF (QS_OFF + 32 * 65)
#define ATTN_SMEM_FLOATS (KV_OFF + 64 * 65)

__global__ __launch_bounds__(256) void attn_kernel(
    const float* __restrict__ Q, const float* __restrict__ Kg,
    const float* __restrict__ V, float* __restrict__ O) {
    extern __shared__ float sm[];
    float* scoresT = sm;
    float* Qs = sm + QS_OFF;
    float* KVs = sm + KV_OFF;

    int tid = threadIdx.x;
    int qt = blockIdx.x;
    int hh = blockIdx.y;
    int sg = blockIdx.z;
    int qbase = sg * SEGLEN + qt * 32;
    int kbase = sg * SEGLEN;
    int colbase = hh * HD;

#pragma unroll
    for (int i = 0; i < 8; i++) {
        int e = tid + i * 256;
        int q = e >> 6, d = e & 63;
        Qs[q * 65 + d] = Q[(size_t)(qbase + q) * DIM + colbase + d] * 0.125f;
    }
    int ql = tid & 31;
    int grp = tid >> 5;

    for (int kt = 0; kt < 8; kt++) {
        __syncthreads();
#pragma unroll
        for (int i = 0; i < 16; i++) {
            int e = tid + i * 256;
            int k = e >> 6, d = e & 63;
            KVs[k * 65 + d] = Kg[(size_t)(kbase + kt * 64 + k) * DIM + colbase + d];
        }
        __syncthreads();
        float acc[8] = {};
#pragma unroll
        for (int d = 0; d < 64; d++) {
            float qv = Qs[ql * 65 + d];
#pragma unroll
            for (int j = 0; j < 8; j++)
                acc[j] += qv * KVs[(grp * 8 + j) * 65 + d];
        }
#pragma unroll
        for (int j = 0; j < 8; j++)
            scoresT[(kt * 64 + grp * 8 + j) * SCORE_PITCH + ql] = acc[j];
    }
    __syncthreads();

    {
        int w = tid >> 5, l = tid & 31;
        for (int qi = 0; qi < 4; qi++) {
            int q = w + qi * 8;
            float vals[16];
            float m = -1e30f;
#pragma unroll
            for (int s = 0; s < 16; s++) {
                vals[s] = scoresT[(l + s * 32) * SCORE_PITCH + q];
                m = fmaxf(m, vals[s]);
            }
#pragma unroll
            for (int o = 16; o > 0; o >>= 1) m = fmaxf(m, __shfl_xor_sync(0xFFFFFFFFu, m, o));
            float sum = 0.f;
#pragma unroll
            for (int s = 0; s < 16; s++) {
                float e = __expf(vals[s] - m);
                vals[s] = e;
                sum += e;
            }
#pragma unroll
            for (int o = 16; o > 0; o >>= 1) sum += __shfl_xor_sync(0xFFFFFFFFu, sum, o);
            float r = 1.f / sum;
#pragma unroll
            for (int s = 0; s < 16; s++)
                scoresT[(l + s * 32) * SCORE_PITCH + q] = vals[s] * r;
        }
    }

    float o[8] = {};
    for (int vt = 0; vt < 8; vt++) {
        __syncthreads();
#pragma unroll
        for (int i = 0; i < 16; i++) {
            int e = tid + i * 256;
            int k = e >> 6, d = e & 63;
            KVs[k * 65 + d] = V[(size_t)(kbase + vt * 64 + k) * DIM + colbase + d];
        }
        __syncthreads();
#pragma unroll
        for (int kk = 0; kk < 64; kk++) {
            float p = scoresT[(vt * 64 + kk) * SCORE_PITCH + ql];
#pragma unroll
            for (int j = 0; j < 8; j++)
                o[j] += p * KVs[kk * 65 + grp * 8 + j];
        }
    }

    float4* dst = (float4*)&O[(size_t)(qbase + ql) * DIM + colbase + grp * 8];
    dst[0] = make_float4(o[0], o[1], o[2], o[3]);
    dst[1] = make_float4(o[4], o[5], o[6], o[7]);
}

// ---------------- launch ----------------
extern "C" void kernel_launch(void* const* d_in, const int* in_sizes, int n_in,
                              void* d_out, int out_size) {
    const float* hidden = (const float*)d_in[0];
    const float* Wq = (const float*)d_in[2];
    const float* bq = (const float*)d_in[3];
    const float* Wk = (const float*)d_in[4];
    const float* Wv = (const float*)d_in[5];
    const float* bv = (const float*)d_in[6];
    const float* Wo = (const float*)d_in[7];
    const float* bo = (const float*)d_in[8];
    const float* g1 = (const float*)d_in[9];
    const float* b1 = (const float*)d_in[10];
    const float* Wf1 = (const float*)d_in[11];
    const float* bf1 = (const float*)d_in[12];
    const float* Wf2 = (const float*)d_in[13];
    const float* bf2 = (const float*)d_in[14];
    const float* g2 = (const float*)d_in[15];
    const float* b2 = (const float*)d_in[16];
    float* out = (float*)d_out;

    float *xln, *q, *k, *v, *attn, *h, *yln, *mid;
    float *wqt, *wkt, *wvt, *wot, *wf1t, *wf2t;
    cudaGetSymbolAddress((void**)&xln, g_xln);
    cudaGetSymbolAddress((void**)&q, g_q);
    cudaGetSymbolAddress((void**)&k, g_k);
    cudaGetSymbolAddress((void**)&v, g_v);
    cudaGetSymbolAddress((void**)&attn, g_attn);
    cudaGetSymbolAddress((void**)&h, g_h);
    cudaGetSymbolAddress((void**)&yln, g_yln);
    cudaGetSymbolAddress((void**)&mid, g_mid);
    cudaGetSymbolAddress((void**)&wqt, g_wqt);
    cudaGetSymbolAddress((void**)&wkt, g_wkt);
    cudaGetSymbolAddress((void**)&wvt, g_wvt);
    cudaGetSymbolAddress((void**)&wot, g_wot);
    cudaGetSymbolAddress((void**)&wf1t, g_wf1t);
    cudaGetSymbolAddress((void**)&wf2t, g_wf2t);

    const int ATTN_SMEM = ATTN_SMEM_FLOATS * 4;
    cudaFuncSetAttribute(attn_kernel, cudaFuncAttributeMaxDynamicSharedMemorySize, ATTN_SMEM);
    cudaFuncSetAttribute(mma_gemm<EPI_NONE>, cudaFuncAttributeMaxDynamicSharedMemorySize, GEMM_DSMEM);
    cudaFuncSetAttribute(mma_gemm<EPI_BIAS>, cudaFuncAttributeMaxDynamicSharedMemorySize, GEMM_DSMEM);
    cudaFuncSetAttribute(mma_gemm<EPI_GELU>, cudaFuncAttributeMaxDynamicSharedMemorySize, GEMM_DSMEM);
    cudaFuncSetAttribute(mma_gemm<EPI_BIAS_RES>, cudaFuncAttributeMaxDynamicSharedMemorySize, GEMM_DSMEM);

    dim3 tb(32, 8);
    // weight transposes ([R,C] -> [C,R]) so every GEMM B operand is K-major
    transpose_k<<<dim3(DIM / 32, DIM / 32), tb>>>(Wq, wqt, DIM, DIM);
    transpose_k<<<dim3(DIM / 32, DIM / 32), tb>>>(Wk, wkt, DIM, DIM);
    transpose_k<<<dim3(DIM / 32, DIM / 32), tb>>>(Wv, wvt, DIM, DIM);
    transpose_k<<<dim3(FFNDIM / 32, DIM / 32), tb>>>(Wf1, wf1t, DIM, FFNDIM);
    transpose_k<<<dim3(DIM / 32, DIM / 32), tb>>>(Wo, wot, DIM, DIM);
    transpose_k<<<dim3(DIM / 32, FFNDIM / 32), tb>>>(Wf2, wf2t, FFNDIM, DIM);

    dim3 gD(DIM / 128, SEQ / 128);
    dim3 gF(FFNDIM / 128, SEQ / 128);

    // LN1
    ln_kernel<<<SEQ, 256>>>(hidden, g1, b1, xln);
    // QKV (tf32 tensor core)
    mma_gemm<EPI_BIAS><<<gD, 256, GEMM_DSMEM>>>(xln, wqt, bq, nullptr, q, DIM, DIM);
    mma_gemm<EPI_NONE><<<gD, 256, GEMM_DSMEM>>>(xln, wkt, nullptr, nullptr, k, DIM, DIM);
    mma_gemm<EPI_BIAS><<<gD, 256, GEMM_DSMEM>>>(xln, wvt, bv, nullptr, v, DIM, DIM);
    // attention (block-diagonal, 512-token segments)
    attn_kernel<<<dim3(16, NH, 8), 256, ATTN_SMEM>>>(q, k, v, attn);
    // O proj + residual
    mma_gemm<EPI_BIAS_RES><<<gD, 256, GEMM_DSMEM>>>(attn, wot, bo, hidden, h, DIM, DIM);
    // LN2
    ln_kernel<<<SEQ, 256>>>(h, g2, b2, yln);
    // FFN
    mma_gemm<EPI_GELU><<<gF, 256, GEMM_DSMEM>>>(yln, wf1t, bf1, nullptr, mid, FFNDIM, DIM);
    mma_gemm<EPI_BIAS_RES><<<gD, 256, GEMM_DSMEM>>>(mid, wf2t, bf2, h, out, DIM, FFNDIM);
}